// round 10
// baseline (speedup 1.0000x reference)
#include <cuda_runtime.h>

typedef unsigned long long u64;

#define CB  2048
#define CT  512
#define CI  64
#define CH  32
#define CG  128

// Scratch: g_xg[((t*CB + b)*32 + j)*2 + {0,1}] = {(xg_i,xg_f),(xg_g,xg_o)} for unit j.
// One extra timestep slab so K2's t+1 prefetch never reads OOB.
__device__ u64 g_xg[(size_t)(CT + 1) * CB * 64];

__device__ __forceinline__ u64 ffma2(u64 a, u64 b, u64 c) {
    u64 d;
    asm("fma.rn.f32x2 %0, %1, %2, %3;" : "=l"(d) : "l"(a), "l"(b), "l"(c));
    return d;
}
__device__ __forceinline__ u64 addx2(u64 a, u64 b) {
    u64 d;
    asm("add.rn.f32x2 %0, %1, %2;" : "=l"(d) : "l"(a), "l"(b));
    return d;
}
__device__ __forceinline__ u64 pack2(float lo, float hi) {
    u64 d;
    asm("mov.b64 %0, {%1, %2};" : "=l"(d) : "f"(lo), "f"(hi));
    return d;
}
__device__ __forceinline__ float2 unpack2(u64 v) {
    float2 r;
    asm("mov.b64 {%0, %1}, %2;" : "=f"(r.x), "=f"(r.y) : "l"(v));
    return r;
}

// ---------------------------------------------------------------------------
// K1: input projection, flattened GEMM over rows m = b*CT + t.
// Block 256 thr, 8 tiles of 128 rows, single-buffered xs staged PRE-DUPLICATED
// as u64 {x,x} -> inner loop has ZERO packs: 4 LDS.128 (x-dup, broadcast) +
// 2x2 LDS.64 (weights, dense) + 32 FFMA2 per k.
// Thread: units jj = tx, tx+16 (q=0,1); gate-pairs (i,f),(g,o) in f32x2;
// 8 scalar rows. acc u64s are ALREADY in scratch format -> dense 16B stores.
// ---------------------------------------------------------------------------
#define WTS  65       // u64 stride per k-row of weights (64 + 1 pad)
#define XTS2 130      // u64 stride per k-row of dup'd x (128 + 2 pad)
#define K1T  8        // row-tiles per block

extern __shared__ char sm1[];

__global__ __launch_bounds__(256, 2) void k1_inproj(
    const float* __restrict__ x, const float* __restrict__ Wih,
    const float* __restrict__ bih, const float* __restrict__ bhh)
{
    u64* Wt  = (u64*)sm1;                      // Wt[k*WTS + cls*16 + tx]
    u64* xs2 = (u64*)(sm1 + 64 * WTS * 8);     // xs2[k*XTS2 + row] = {x,x}
    const int tid = threadIdx.x;
    const size_t m0 = (size_t)blockIdx.x * (128 * K1T);

    // Stage gate-paired weights: cls = q*2+pp, unit u = u0 + 16q.
    // Wt[k][cls*16+u0] = {W[u + pp*64][k], W[u+32 + pp*64][k]}
    #pragma unroll
    for (int idx = tid; idx < 64 * 64; idx += 256) {
        int k = idx >> 6, e = idx & 63;
        int cls = e >> 4, u0 = e & 15;
        int q = cls >> 1, pp = cls & 1;
        int u = u0 + q * 16;
        Wt[k * WTS + e] = pack2(Wih[(u + pp * 64) * 64 + k],
                                Wih[(u + 32 + pp * 64) * 64 + k]);
    }

    const int tx = tid & 15, ty = tid >> 4;
    const int r0 = ty * 8;
    const int mr = tid >> 4, kq = tid & 15;   // staging coords (row, float4-col)

    // Bias pairs: bd[q][pp] = {b[jj + pp*64], b[jj+32 + pp*64]}, jj = tx+16q
    u64 bd[2][2];
    #pragma unroll
    for (int q = 0; q < 2; q++)
        #pragma unroll
        for (int pp = 0; pp < 2; pp++) {
            int g = tx + 16 * q + pp * 64;
            bd[q][pp] = pack2(bih[g] + bhh[g], bih[g + 32] + bhh[g + 32]);
        }

    const float4* x4 = (const float4*)x;   // 16 float4 per row

    // Prologue: load tile 0
    float4 nxt[8];
    #pragma unroll
    for (int i = 0; i < 8; i++)
        nxt[i] = x4[(m0 + mr + i * 16) * 16 + kq];

    for (int tile = 0; tile < K1T; tile++) {
        const size_t mt = m0 + (size_t)tile * 128;

        __syncthreads();   // previous k-loop done with xs2
        // Stage pre-duplicated: xs2[(4kq+c)][row] = {v, v}
        #pragma unroll
        for (int i = 0; i < 8; i++) {
            const int row = mr + i * 16;
            u64* d = &xs2[(4 * kq) * XTS2 + row];
            d[0 * XTS2] = pack2(nxt[i].x, nxt[i].x);
            d[1 * XTS2] = pack2(nxt[i].y, nxt[i].y);
            d[2 * XTS2] = pack2(nxt[i].z, nxt[i].z);
            d[3 * XTS2] = pack2(nxt[i].w, nxt[i].w);
        }
        __syncthreads();

        // Prefetch next tile (LDGs fly under the k-loop)
        if (tile + 1 < K1T) {
            #pragma unroll
            for (int i = 0; i < 8; i++)
                nxt[i] = x4[(mt + 128 + mr + i * 16) * 16 + kq];
        }

        u64 acc[2][2][8];
        #pragma unroll
        for (int q = 0; q < 2; q++)
            #pragma unroll
            for (int pp = 0; pp < 2; pp++)
                #pragma unroll
                for (int r = 0; r < 8; r++) acc[q][pp][r] = bd[q][pp];

        #pragma unroll 4
        for (int k = 0; k < CI; k++) {
            const ulonglong2 xA = *(const ulonglong2*)&xs2[k * XTS2 + r0];
            const ulonglong2 xB = *(const ulonglong2*)&xs2[k * XTS2 + r0 + 2];
            const ulonglong2 xC = *(const ulonglong2*)&xs2[k * XTS2 + r0 + 4];
            const ulonglong2 xD = *(const ulonglong2*)&xs2[k * XTS2 + r0 + 6];
            u64 xd[8] = {xA.x, xA.y, xB.x, xB.y, xC.x, xC.y, xD.x, xD.y};
            #pragma unroll
            for (int q = 0; q < 2; q++) {
                const u64 wif_ = Wt[k * WTS + q * 32 + tx];        // LDS.64 dense
                const u64 wgo_ = Wt[k * WTS + q * 32 + 16 + tx];   // LDS.64 dense
                #pragma unroll
                for (int r = 0; r < 8; r++) {
                    acc[q][0][r] = ffma2(xd[r], wif_, acc[q][0][r]);
                    acc[q][1][r] = ffma2(xd[r], wgo_, acc[q][1][r]);
                }
            }
        }

        // Store: dst = g_xg + ((t*CB + b)*64) + jj*2, jj = tx + 16q.
        // b constant per tile (tiles never straddle a batch).
        {
            const int b = (int)(mt >> 9);
            const int tb = (int)(mt & 511) + r0;
            #pragma unroll
            for (int q = 0; q < 2; q++) {
                const int jj = tx + 16 * q;
                #pragma unroll
                for (int r = 0; r < 8; r++) {
                    u64* dst = g_xg + ((size_t)(tb + r) * CB + b) * 64 + jj * 2;
                    ulonglong2 v;
                    v.x = acc[q][0][r];   // {i, f}
                    v.y = acc[q][1][r];   // {g, o}
                    *(ulonglong2*)dst = v;
                }
            }
        }
    }
}

// ---------------------------------------------------------------------------
// K2: recurrence, 2-warp k-split with DUPLICATED cells -> single block BAR/t.
// Block = 2 warps / 2 batches. Warp w: k-half [16w,16w+16), 64 weight regs.
// Each warp computes partials for BOTH batches over its k-half; after ONE
// __syncthreads exchange, BOTH warps compute BOTH cells (canonical add order
// -> bit-identical h) and update a PRIVATE per-warp dup'd h array. The k-loop
// reads only its own warp's copy -> h publish needs only __syncwarp.
// Per k: 1 broadcast LDS.128 + 4 FFMA2, zero packs. fc fused.
// ---------------------------------------------------------------------------
__device__ __forceinline__ float sigmf(float v) {
    return __fdividef(1.f, 1.f + __expf(-v));
}
__device__ __forceinline__ float tanhf_fast(float v) {
    return 1.f - __fdividef(2.f, 1.f + __expf(2.f * v));
}
__device__ __forceinline__ void lstm_cell(float gi, float gf, float gg, float go,
                                          float& c, float& h) {
    float iv = sigmf(gi);
    float fv = sigmf(gf);
    float gv = tanhf_fast(gg);
    float ov = sigmf(go);
    c = fv * c + iv * gv;
    h = ov * tanhf_fast(c);
}

__global__ __launch_bounds__(64) void k2_rnn(
    const float* __restrict__ Whh, const float* __restrict__ wfc,
    const float* __restrict__ bfc, float* __restrict__ out)
{
    __shared__ ulonglong2 hs[2][CH];        // per-warp PRIVATE: {<h0,h0>,<h1,h1>}
    __shared__ ulonglong2 pex[2][2][CH];    // [batch][warp][j] = {if, go} partial

    const int tid = threadIdx.x;
    const int j   = tid & 31;           // hidden unit
    const int w   = tid >> 5;           // warp id: k-half + which xg it loads
    const int b0  = blockIdx.x * 2;     // batches b0, b0+1
    const int kb  = w * 16;

    // Register weights for this warp's k-half, gate-paired per unit j
    u64 wif[16], wgo[16];
    #pragma unroll
    for (int kk = 0; kk < 16; kk++) {
        int k = kb + kk;
        wif[kk] = pack2(__ldg(&Whh[j * CH + k]),          // i row j
                        __ldg(&Whh[(32 + j) * CH + k]));  // f
        wgo[kk] = pack2(__ldg(&Whh[(64 + j) * CH + k]),   // g
                        __ldg(&Whh[(96 + j) * CH + k]));  // o
    }

    {
        ulonglong2 z;
        z.x = 0ull;  z.y = 0ull;
        hs[w][j] = z;
    }
    float h0 = 0.f, h1 = 0.f, c0 = 0.f, c1 = 0.f;
    const float wfcv = wfc[j];
    __syncthreads();

    // Warp w loads xg for batch b0+w only.
    const u64* xptr = g_xg + ((size_t)(b0 + w)) * 64 + j * 2;
    const size_t TSTRIDE = (size_t)CB * 64;

    ulonglong2 xc = *(const ulonglong2*)xptr;
    xptr += TSTRIDE;

    for (int t = 0; t < CT; t++) {
        ulonglong2 xn = *(const ulonglong2*)xptr;
        xptr += TSTRIDE;

        // Partials over this warp's k-half, for both batches.
        // xg of batch (b0+w) is folded into this warp's partial for that batch.
        u64 s_if[2], s_go[2];
        s_if[w]     = xc.x;  s_go[w]     = xc.y;
        s_if[1 - w] = 0ull;  s_go[1 - w] = 0ull;

        #pragma unroll
        for (int kk = 0; kk < 16; kk++) {
            const ulonglong2 hd = hs[w][kb + kk];   // own-warp copy, broadcast
            s_if[0] = ffma2(hd.x, wif[kk], s_if[0]);
            s_go[0] = ffma2(hd.x, wgo[kk], s_go[0]);
            s_if[1] = ffma2(hd.y, wif[kk], s_if[1]);
            s_go[1] = ffma2(hd.y, wgo[kk], s_go[1]);
        }

        // Exchange partials (single block barrier per timestep)
        {
            ulonglong2 p0, p1;
            p0.x = s_if[0];  p0.y = s_go[0];
            p1.x = s_if[1];  p1.y = s_go[1];
            pex[0][w][j] = p0;
            pex[1][w][j] = p1;
        }
        __syncthreads();

        // Full sums in canonical order: add(warp0_part, warp1_part) in BOTH
        // warps -> bit-identical results.
        u64 f0_if, f0_go, f1_if, f1_go;
        if (w == 0) {
            const ulonglong2 o0 = pex[0][1][j];
            const ulonglong2 o1 = pex[1][1][j];
            f0_if = addx2(s_if[0], o0.x);  f0_go = addx2(s_go[0], o0.y);
            f1_if = addx2(s_if[1], o1.x);  f1_go = addx2(s_go[1], o1.y);
        } else {
            const ulonglong2 o0 = pex[0][0][j];
            const ulonglong2 o1 = pex[1][0][j];
            f0_if = addx2(o0.x, s_if[0]);  f0_go = addx2(o0.y, s_go[0]);
            f1_if = addx2(o1.x, s_if[1]);  f1_go = addx2(o1.y, s_go[1]);
        }

        // Both warps compute BOTH cells (identical results)
        {
            float2 gif = unpack2(f0_if);
            float2 ggo = unpack2(f0_go);
            lstm_cell(gif.x, gif.y, ggo.x, ggo.y, c0, h0);
        }
        {
            float2 gif = unpack2(f1_if);
            float2 ggo = unpack2(f1_go);
            lstm_cell(gif.x, gif.y, ggo.x, ggo.y, c1, h1);
        }

        // Publish to OWN warp's private h array: warp-local sync only.
        {
            ulonglong2 v;
            v.x = pack2(h0, h0);
            v.y = pack2(h1, h1);
            hs[w][j] = v;
        }
        __syncwarp();

        xc = xn;
    }

    // Fused fc: warp w outputs batch b0+w (it has both h's; pick its own).
    float hv = (w == 0) ? h0 : h1;
    float v = hv * wfcv;
    #pragma unroll
    for (int off = 16; off > 0; off >>= 1)
        v += __shfl_xor_sync(0xffffffffu, v, off);
    if (j == 0) out[b0 + w] = v + bfc[0];
}

// ---------------------------------------------------------------------------
extern "C" void kernel_launch(void* const* d_in, const int* in_sizes, int n_in,
                              void* d_out, int out_size)
{
    const float* x   = (const float*)d_in[0];
    const float* Wih = (const float*)d_in[1];
    const float* Whh = (const float*)d_in[2];
    const float* bih = (const float*)d_in[3];
    const float* bhh = (const float*)d_in[4];
    const float* Wfc = (const float*)d_in[5];
    const float* bfc = (const float*)d_in[6];
    float* out = (float*)d_out;

    const int smem1 = 64 * WTS * 8 + 64 * XTS2 * 8;  // 33280 + 66560 = 99840 B
    cudaFuncSetAttribute(k1_inproj, cudaFuncAttributeMaxDynamicSharedMemorySize, smem1);

    const int g1 = (CB * CT) / (128 * K1T);   // 1024 blocks
    k1_inproj<<<g1, 256, smem1>>>(x, Wih, bih, bhh);
    k2_rnn<<<CB / 2, 64>>>(Whh, Wfc, bfc, out);
}

// round 13
// speedup vs baseline: 1.0833x; 1.0833x over previous
#include <cuda_runtime.h>

typedef unsigned long long u64;

#define CB  2048
#define CT  512
#define CI  64
#define CH  32
#define CG  128

// Scratch: g_xg[((t*CB + b)*32 + j)*2 + {0,1}] = {(xg_i,xg_f),(xg_g,xg_o)} for unit j.
// One extra timestep slab so K2's t+1 prefetch never reads OOB.
__device__ u64 g_xg[(size_t)(CT + 1) * CB * 64];

__device__ __forceinline__ u64 ffma2(u64 a, u64 b, u64 c) {
    u64 d;
    asm("fma.rn.f32x2 %0, %1, %2, %3;" : "=l"(d) : "l"(a), "l"(b), "l"(c));
    return d;
}
__device__ __forceinline__ u64 pack2(float lo, float hi) {
    u64 d;
    asm("mov.b64 %0, {%1, %2};" : "=l"(d) : "f"(lo), "f"(hi));
    return d;
}
__device__ __forceinline__ float2 unpack2(u64 v) {
    float2 r;
    asm("mov.b64 {%0, %1}, %2;" : "=f"(r.x), "=f"(r.y) : "l"(v));
    return r;
}

// ---------------------------------------------------------------------------
// K1: input projection, flattened GEMM over rows m = b*CT + t.  (R9 version,
// measured ~417us.) Block 256 thr, 8 tiles of 128 rows, xs staged
// PRE-DUPLICATED as u64 {x,x} -> zero packs in the k-loop:
// 4 LDS.128 (x-dup) + 4 LDS.64 (weights, dense) + 32 FFMA2 per k.
// acc u64s are ALREADY in scratch format -> dense 16B stores.
// ---------------------------------------------------------------------------
#define WTS  65       // u64 stride per k-row of weights (64 + 1 pad)
#define XTS2 130      // u64 stride per k-row of dup'd x (128 + 2 pad)
#define K1T  8        // row-tiles per block

extern __shared__ char sm1[];

__global__ __launch_bounds__(256, 2) void k1_inproj(
    const float* __restrict__ x, const float* __restrict__ Wih,
    const float* __restrict__ bih, const float* __restrict__ bhh)
{
    u64* Wt  = (u64*)sm1;                      // Wt[k*WTS + cls*16 + tx]
    u64* xs2 = (u64*)(sm1 + 64 * WTS * 8);     // xs2[k*XTS2 + row] = {x,x}
    const int tid = threadIdx.x;
    const size_t m0 = (size_t)blockIdx.x * (128 * K1T);

    // Stage gate-paired weights: cls = q*2+pp, unit u = u0 + 16q.
    #pragma unroll
    for (int idx = tid; idx < 64 * 64; idx += 256) {
        int k = idx >> 6, e = idx & 63;
        int cls = e >> 4, u0 = e & 15;
        int q = cls >> 1, pp = cls & 1;
        int u = u0 + q * 16;
        Wt[k * WTS + e] = pack2(Wih[(u + pp * 64) * 64 + k],
                                Wih[(u + 32 + pp * 64) * 64 + k]);
    }

    const int tx = tid & 15, ty = tid >> 4;
    const int r0 = ty * 8;
    const int mr = tid >> 4, kq = tid & 15;   // staging coords

    // Bias pairs: bd[q][pp] = {b[jj + pp*64], b[jj+32 + pp*64]}, jj = tx+16q
    u64 bd[2][2];
    #pragma unroll
    for (int q = 0; q < 2; q++)
        #pragma unroll
        for (int pp = 0; pp < 2; pp++) {
            int g = tx + 16 * q + pp * 64;
            bd[q][pp] = pack2(bih[g] + bhh[g], bih[g + 32] + bhh[g + 32]);
        }

    const float4* x4 = (const float4*)x;   // 16 float4 per row

    float4 nxt[8];
    #pragma unroll
    for (int i = 0; i < 8; i++)
        nxt[i] = x4[(m0 + mr + i * 16) * 16 + kq];

    for (int tile = 0; tile < K1T; tile++) {
        const size_t mt = m0 + (size_t)tile * 128;

        __syncthreads();
        #pragma unroll
        for (int i = 0; i < 8; i++) {
            const int row = mr + i * 16;
            u64* d = &xs2[(4 * kq) * XTS2 + row];
            d[0 * XTS2] = pack2(nxt[i].x, nxt[i].x);
            d[1 * XTS2] = pack2(nxt[i].y, nxt[i].y);
            d[2 * XTS2] = pack2(nxt[i].z, nxt[i].z);
            d[3 * XTS2] = pack2(nxt[i].w, nxt[i].w);
        }
        __syncthreads();

        if (tile + 1 < K1T) {
            #pragma unroll
            for (int i = 0; i < 8; i++)
                nxt[i] = x4[(mt + 128 + mr + i * 16) * 16 + kq];
        }

        u64 acc[2][2][8];
        #pragma unroll
        for (int q = 0; q < 2; q++)
            #pragma unroll
            for (int pp = 0; pp < 2; pp++)
                #pragma unroll
                for (int r = 0; r < 8; r++) acc[q][pp][r] = bd[q][pp];

        #pragma unroll 4
        for (int k = 0; k < CI; k++) {
            const ulonglong2 xA = *(const ulonglong2*)&xs2[k * XTS2 + r0];
            const ulonglong2 xB = *(const ulonglong2*)&xs2[k * XTS2 + r0 + 2];
            const ulonglong2 xC = *(const ulonglong2*)&xs2[k * XTS2 + r0 + 4];
            const ulonglong2 xD = *(const ulonglong2*)&xs2[k * XTS2 + r0 + 6];
            u64 xd[8] = {xA.x, xA.y, xB.x, xB.y, xC.x, xC.y, xD.x, xD.y};
            #pragma unroll
            for (int q = 0; q < 2; q++) {
                const u64 wif_ = Wt[k * WTS + q * 32 + tx];
                const u64 wgo_ = Wt[k * WTS + q * 32 + 16 + tx];
                #pragma unroll
                for (int r = 0; r < 8; r++) {
                    acc[q][0][r] = ffma2(xd[r], wif_, acc[q][0][r]);
                    acc[q][1][r] = ffma2(xd[r], wgo_, acc[q][1][r]);
                }
            }
        }

        {
            const int b = (int)(mt >> 9);
            const int tb = (int)(mt & 511) + r0;
            #pragma unroll
            for (int q = 0; q < 2; q++) {
                const int jj = tx + 16 * q;
                #pragma unroll
                for (int r = 0; r < 8; r++) {
                    u64* dst = g_xg + ((size_t)(tb + r) * CB + b) * 64 + jj * 2;
                    ulonglong2 v;
                    v.x = acc[q][0][r];   // {i, f}
                    v.y = acc[q][1][r];   // {g, o}
                    *(ulonglong2*)dst = v;
                }
            }
        }
    }
}

// ---------------------------------------------------------------------------
// K2: recurrence (R5 shuffle structure, measured 343us, + grouped shuffles).
// Each warp owns 2 batches, fully independent (no barriers, no smem).
// W_hh register-resident gate-paired (64 u64). h broadcast via __shfl_sync,
// batched 8 k's at a time: 16 SHFLs issue back-to-back (MLP on MIO), then
// 8 x (2 pack + 4 FFMA2). Only the first group's SHFL latency is exposed.
// ---------------------------------------------------------------------------
__device__ __forceinline__ float sigmf(float v) {
    return __fdividef(1.f, 1.f + __expf(-v));
}
__device__ __forceinline__ float tanhf_fast(float v) {
    return 1.f - __fdividef(2.f, 1.f + __expf(2.f * v));
}
__device__ __forceinline__ void lstm_cell(float gi, float gf, float gg, float go,
                                          float& c, float& h) {
    float iv = sigmf(gi);
    float fv = sigmf(gf);
    float gv = tanhf_fast(gg);
    float ov = sigmf(go);
    c = fv * c + iv * gv;
    h = ov * tanhf_fast(c);
}

#define K2W 2   // warps per block

__global__ __launch_bounds__(32 * K2W) void k2_rnn(
    const float* __restrict__ Whh, const float* __restrict__ wfc,
    const float* __restrict__ bfc, float* __restrict__ out)
{
    const int tid = threadIdx.x;
    const int j   = tid & 31;
    const int gw  = blockIdx.x * K2W + (tid >> 5);
    const int b0  = gw * 2;

    // Register-resident recurrent weights, gate-paired per unit j
    u64 wif[CH], wgo[CH];
    #pragma unroll
    for (int k = 0; k < CH; k++) {
        wif[k] = pack2(__ldg(&Whh[(0 * CH + j) * CH + k]),
                       __ldg(&Whh[(1 * CH + j) * CH + k]));
        wgo[k] = pack2(__ldg(&Whh[(2 * CH + j) * CH + k]),
                       __ldg(&Whh[(3 * CH + j) * CH + k]));
    }

    float h0 = 0.f, h1 = 0.f, c0 = 0.f, c1 = 0.f;
    const float wfcv = wfc[j];

    const u64* xptr = g_xg + ((size_t)b0) * 64 + j * 2;
    const size_t TSTRIDE = (size_t)CB * 64;

    ulonglong2 xc0 = *(const ulonglong2*)(xptr);
    ulonglong2 xc1 = *(const ulonglong2*)(xptr + 64);
    xptr += TSTRIDE;

    for (int t = 0; t < CT; t++) {
        ulonglong2 xn0 = *(const ulonglong2*)(xptr);
        ulonglong2 xn1 = *(const ulonglong2*)(xptr + 64);
        xptr += TSTRIDE;

        u64 a0_if = xc0.x, a0_go = xc0.y;
        u64 a1_if = xc1.x, a1_go = xc1.y;

        // Grouped: batch 16 shuffles, then 8 k's of math.
        #pragma unroll
        for (int kb = 0; kb < CH; kb += 8) {
            float v0[8], v1[8];
            #pragma unroll
            for (int kk = 0; kk < 8; kk++) {
                v0[kk] = __shfl_sync(0xffffffffu, h0, kb + kk);
                v1[kk] = __shfl_sync(0xffffffffu, h1, kb + kk);
            }
            #pragma unroll
            for (int kk = 0; kk < 8; kk++) {
                u64 d0 = pack2(v0[kk], v0[kk]);
                u64 d1 = pack2(v1[kk], v1[kk]);
                a0_if = ffma2(d0, wif[kb + kk], a0_if);
                a0_go = ffma2(d0, wgo[kb + kk], a0_go);
                a1_if = ffma2(d1, wif[kb + kk], a1_if);
                a1_go = ffma2(d1, wgo[kb + kk], a1_go);
            }
        }

        float2 p0 = unpack2(a0_if);   // {i, f}
        float2 p1 = unpack2(a0_go);   // {g, o}
        lstm_cell(p0.x, p0.y, p1.x, p1.y, c0, h0);
        float2 q0 = unpack2(a1_if);
        float2 q1 = unpack2(a1_go);
        lstm_cell(q0.x, q0.y, q1.x, q1.y, c1, h1);

        xc0 = xn0;  xc1 = xn1;
    }

    // Fused fc: out[b] = sum_j h[b][j] * W_fc[0][j] + b_fc
    float v0 = h0 * wfcv;
    float v1 = h1 * wfcv;
    #pragma unroll
    for (int off = 16; off > 0; off >>= 1) {
        v0 += __shfl_xor_sync(0xffffffffu, v0, off);
        v1 += __shfl_xor_sync(0xffffffffu, v1, off);
    }
    if (j == 0) {
        float bb = bfc[0];
        out[b0]     = v0 + bb;
        out[b0 + 1] = v1 + bb;
    }
}

// ---------------------------------------------------------------------------
extern "C" void kernel_launch(void* const* d_in, const int* in_sizes, int n_in,
                              void* d_out, int out_size)
{
    const float* x   = (const float*)d_in[0];
    const float* Wih = (const float*)d_in[1];
    const float* Whh = (const float*)d_in[2];
    const float* bih = (const float*)d_in[3];
    const float* bhh = (const float*)d_in[4];
    const float* Wfc = (const float*)d_in[5];
    const float* bfc = (const float*)d_in[6];
    float* out = (float*)d_out;

    const int smem1 = 64 * WTS * 8 + 64 * XTS2 * 8;  // 33280 + 66560 = 99840 B
    cudaFuncSetAttribute(k1_inproj, cudaFuncAttributeMaxDynamicSharedMemorySize, smem1);

    const int g1 = (CB * CT) / (128 * K1T);   // 1024 blocks
    k1_inproj<<<g1, 256, smem1>>>(x, Wih, bih, bhh);
    k2_rnn<<<CB / (2 * K2W), 32 * K2W>>>(Whh, Wfc, bfc, out);
}

// round 15
// speedup vs baseline: 1.4905x; 1.3758x over previous
#include <cuda_runtime.h>
#include <cuda_bf16.h>
#include <mma.h>
#include <cstdint>

using namespace nvcuda;

typedef unsigned long long u64;
typedef unsigned int u32;

#define CB 2048
#define CT 512
#define CH 32

// Scratch: raw gate preactivations (no bias), xg[m*128 + g], m = b*CT + t.
// +CT rows padding so K2's t+1 prefetch never reads OOB.
__device__ float g_xg[((size_t)CB * CT + CT) * 128];

// ---------------- f32x2 helpers ----------------
__device__ __forceinline__ u64 ffma2(u64 a, u64 b, u64 c) {
    u64 d;
    asm("fma.rn.f32x2 %0, %1, %2, %3;" : "=l"(d) : "l"(a), "l"(b), "l"(c));
    return d;
}
__device__ __forceinline__ u64 addx2(u64 a, u64 b) {
    u64 d;
    asm("add.rn.f32x2 %0, %1, %2;" : "=l"(d) : "l"(a), "l"(b));
    return d;
}
__device__ __forceinline__ u64 pack2(float lo, float hi) {
    u64 d;
    asm("mov.b64 %0, {%1, %2};" : "=l"(d) : "f"(lo), "f"(hi));
    return d;
}
__device__ __forceinline__ float2 unpack2(u64 v) {
    float2 r;
    asm("mov.b64 {%0, %1}, %2;" : "=f"(r.x), "=f"(r.y) : "l"(v));
    return r;
}
__device__ __forceinline__ u32 bfpair(float hi_, float lo_) {
    u32 d;
    asm("cvt.rn.bf16x2.f32 %0, %1, %2;" : "=r"(d) : "f"(hi_), "f"(lo_));
    return d;
}

// Split a float4 into bf16-hi pairs and bf16-lo (residual) pairs.
__device__ __forceinline__ void bf16split(float4 v, u32& h01, u32& h23,
                                          u32& l01, u32& l23) {
    h01 = bfpair(v.y, v.x);
    float q0 = v.x - __uint_as_float(h01 << 16);
    float q1 = v.y - __uint_as_float(h01 & 0xFFFF0000u);
    l01 = bfpair(q1, q0);
    h23 = bfpair(v.w, v.z);
    float q2 = v.z - __uint_as_float(h23 << 16);
    float q3 = v.w - __uint_as_float(h23 & 0xFFFF0000u);
    l23 = bfpair(q3, q2);
}

// ---------------------------------------------------------------------------
// K1: xg GEMM on tensor cores (wmma bf16, split precision).
//   C[1M x 128] = A[1M x 192] x B[192 x 128]
//   A = [xh | xl | xh] (row-major),  B = [Wh ; Wh ; Wl] (col-major smem).
// Block: 256 thr (8 warps), 8 tiles of 128 rows. B staged once per block.
// Warp (wm = w>>2, wn = w&3): 4 m-tiles x 2 n-tiles of 16x16, 12 k-steps.
// Epilogue: store_matrix_sync straight to global f32 scratch (bias in K2).
// ---------------------------------------------------------------------------
#define ASTR 208   // bf16 elems per A row (192 + 16 pad; 416B, 32B-aligned)
#define BSTR 208   // bf16 elems per B column
#define K1T  8

#define SM_A 0
#define SM_B (128 * ASTR * 2)
#define SM_TOT (128 * ASTR * 2 + 128 * BSTR * 2)   // 106,496 B

extern __shared__ char sm1[];

__global__ __launch_bounds__(256, 2) void k1_wmma(
    const float* __restrict__ x, const float* __restrict__ Wih)
{
    __nv_bfloat16* As = (__nv_bfloat16*)(sm1 + SM_A);
    __nv_bfloat16* Bs = (__nv_bfloat16*)(sm1 + SM_B);
    u32* As32 = (u32*)As;
    u32* Bs32 = (u32*)Bs;

    const int tid = threadIdx.x;
    const size_t m0 = (size_t)blockIdx.x * (128 * K1T);

    // ---- Stage B once: Bs[n*BSTR + k] = Bsplit[k][n] (col-major) ----
    {
        const float4* W4 = (const float4*)Wih;   // 16 float4 per gate row
        #pragma unroll
        for (int i = 0; i < 8; i++) {
            int idx = i * 256 + tid;
            int n = idx >> 4, kq = idx & 15;
            u32 h01, h23, l01, l23;
            bf16split(W4[n * 16 + kq], h01, h23, l01, l23);
            int base = n * (BSTR / 2) + 2 * kq;
            Bs32[base]      = h01;  Bs32[base + 1]  = h23;   // k[0:64)   = Wh
            Bs32[base + 32] = h01;  Bs32[base + 33] = h23;   // k[64:128) = Wh
            Bs32[base + 64] = l01;  Bs32[base + 65] = l23;   // k[128:192)= Wl
        }
    }

    const float4* x4 = (const float4*)x;   // 16 float4 per row

    // Prologue: prefetch tile 0
    float4 nxt[8];
    #pragma unroll
    for (int i = 0; i < 8; i++) {
        int idx = i * 256 + tid;
        nxt[i] = x4[(m0 + (idx >> 4)) * 16 + (idx & 15)];
    }

    const int w  = tid >> 5;
    const int wm = w >> 2;          // m-half: rows [wm*64, wm*64+64)
    const int wn = w & 3;           // n-block: cols [wn*32, wn*32+32)

    for (int tl = 0; tl < K1T; tl++) {
        const size_t mt = m0 + (size_t)tl * 128;

        __syncthreads();   // previous tile's wmma loads done with As
        // Stage A: As[r*ASTR + k]: [0:64)=xh, [64:128)=xl, [128:192)=xh
        #pragma unroll
        for (int i = 0; i < 8; i++) {
            int idx = i * 256 + tid;
            int r = idx >> 4, kq = idx & 15;
            u32 h01, h23, l01, l23;
            bf16split(nxt[i], h01, h23, l01, l23);
            int base = r * (ASTR / 2) + 2 * kq;
            As32[base]      = h01;  As32[base + 1]  = h23;
            As32[base + 32] = l01;  As32[base + 33] = l23;
            As32[base + 64] = h01;  As32[base + 65] = h23;
        }
        __syncthreads();

        // Prefetch next tile (LDGs in flight under the MMAs)
        if (tl + 1 < K1T) {
            #pragma unroll
            for (int i = 0; i < 8; i++) {
                int idx = i * 256 + tid;
                nxt[i] = x4[(mt + 128 + (idx >> 4)) * 16 + (idx & 15)];
            }
        }

        // ---- wmma compute ----
        wmma::fragment<wmma::accumulator, 16, 16, 16, float> acc[4][2];
        #pragma unroll
        for (int i = 0; i < 4; i++)
            #pragma unroll
            for (int jn = 0; jn < 2; jn++)
                wmma::fill_fragment(acc[i][jn], 0.0f);

        #pragma unroll
        for (int ks = 0; ks < 12; ks++) {
            wmma::fragment<wmma::matrix_a, 16, 16, 16, __nv_bfloat16,
                           wmma::row_major> af[4];
            #pragma unroll
            for (int i = 0; i < 4; i++)
                wmma::load_matrix_sync(
                    af[i], As + (wm * 64 + i * 16) * ASTR + ks * 16, ASTR);
            wmma::fragment<wmma::matrix_b, 16, 16, 16, __nv_bfloat16,
                           wmma::col_major> bf[2];
            #pragma unroll
            for (int jn = 0; jn < 2; jn++)
                wmma::load_matrix_sync(
                    bf[jn], Bs + (wn * 2 + jn) * 16 * BSTR + ks * 16, BSTR);
            #pragma unroll
            for (int i = 0; i < 4; i++)
                #pragma unroll
                for (int jn = 0; jn < 2; jn++)
                    wmma::mma_sync(acc[i][jn], af[i], bf[jn], acc[i][jn]);
        }

        // Store straight to global scratch (f32, row-major, ldm=128)
        #pragma unroll
        for (int i = 0; i < 4; i++)
            #pragma unroll
            for (int jn = 0; jn < 2; jn++)
                wmma::store_matrix_sync(
                    g_xg + (mt + wm * 64 + (size_t)i * 16) * 128
                         + (wn * 2 + jn) * 16,
                    acc[i][jn], 128, wmma::mem_row_major);
    }
}

// ---------------------------------------------------------------------------
// K2: recurrence (measured-340us shuffle form). Each warp owns 2 batches;
// lane j = unit j; W_hh register-resident gate-paired; h broadcast via
// grouped __shfl_sync. Bias folded into accumulator init. fc fused.
// ---------------------------------------------------------------------------
__device__ __forceinline__ float sigmf(float v) {
    return __fdividef(1.f, 1.f + __expf(-v));
}
__device__ __forceinline__ float tanhf_fast(float v) {
    return 1.f - __fdividef(2.f, 1.f + __expf(2.f * v));
}
__device__ __forceinline__ void lstm_cell(float gi, float gf, float gg, float go,
                                          float& c, float& h) {
    float iv = sigmf(gi);
    float fv = sigmf(gf);
    float gv = tanhf_fast(gg);
    float ov = sigmf(go);
    c = fv * c + iv * gv;
    h = ov * tanhf_fast(c);
}

#define K2W 2

__global__ __launch_bounds__(32 * K2W) void k2_rnn(
    const float* __restrict__ Whh, const float* __restrict__ bih,
    const float* __restrict__ bhh, const float* __restrict__ wfc,
    const float* __restrict__ bfc, float* __restrict__ out)
{
    const int tid = threadIdx.x;
    const int j   = tid & 31;
    const int gw  = blockIdx.x * K2W + (tid >> 5);
    const int b0  = gw * 2;

    u64 wif[CH], wgo[CH];
    #pragma unroll
    for (int k = 0; k < CH; k++) {
        wif[k] = pack2(__ldg(&Whh[(0 * CH + j) * CH + k]),
                       __ldg(&Whh[(1 * CH + j) * CH + k]));
        wgo[k] = pack2(__ldg(&Whh[(2 * CH + j) * CH + k]),
                       __ldg(&Whh[(3 * CH + j) * CH + k]));
    }
    const u64 bif = pack2(bih[j] + bhh[j], bih[32 + j] + bhh[32 + j]);
    const u64 bgo = pack2(bih[64 + j] + bhh[64 + j], bih[96 + j] + bhh[96 + j]);

    float h0 = 0.f, h1 = 0.f, c0 = 0.f, c1 = 0.f;
    const float wfcv = wfc[j];

    const float* p0 = g_xg + (size_t)b0 * CT * 128 + j;
    const float* p1 = p0 + (size_t)CT * 128;

    float xi0 = __ldg(p0), xf0 = __ldg(p0 + 32), xg0 = __ldg(p0 + 64), xo0 = __ldg(p0 + 96);
    float xi1 = __ldg(p1), xf1 = __ldg(p1 + 32), xg1 = __ldg(p1 + 64), xo1 = __ldg(p1 + 96);
    p0 += 128;  p1 += 128;

    for (int t = 0; t < CT; t++) {
        float ni0 = __ldg(p0), nf0 = __ldg(p0 + 32), ng0 = __ldg(p0 + 64), no0 = __ldg(p0 + 96);
        float ni1 = __ldg(p1), nf1 = __ldg(p1 + 32), ng1 = __ldg(p1 + 64), no1 = __ldg(p1 + 96);
        p0 += 128;  p1 += 128;

        u64 a0_if = addx2(pack2(xi0, xf0), bif);
        u64 a0_go = addx2(pack2(xg0, xo0), bgo);
        u64 a1_if = addx2(pack2(xi1, xf1), bif);
        u64 a1_go = addx2(pack2(xg1, xo1), bgo);

        #pragma unroll
        for (int kb = 0; kb < CH; kb += 8) {
            float v0[8], v1[8];
            #pragma unroll
            for (int kk = 0; kk < 8; kk++) {
                v0[kk] = __shfl_sync(0xffffffffu, h0, kb + kk);
                v1[kk] = __shfl_sync(0xffffffffu, h1, kb + kk);
            }
            #pragma unroll
            for (int kk = 0; kk < 8; kk++) {
                u64 d0 = pack2(v0[kk], v0[kk]);
                u64 d1 = pack2(v1[kk], v1[kk]);
                a0_if = ffma2(d0, wif[kb + kk], a0_if);
                a0_go = ffma2(d0, wgo[kb + kk], a0_go);
                a1_if = ffma2(d1, wif[kb + kk], a1_if);
                a1_go = ffma2(d1, wgo[kb + kk], a1_go);
            }
        }

        float2 pp0 = unpack2(a0_if);
        float2 pp1 = unpack2(a0_go);
        lstm_cell(pp0.x, pp0.y, pp1.x, pp1.y, c0, h0);
        float2 qq0 = unpack2(a1_if);
        float2 qq1 = unpack2(a1_go);
        lstm_cell(qq0.x, qq0.y, qq1.x, qq1.y, c1, h1);

        xi0 = ni0; xf0 = nf0; xg0 = ng0; xo0 = no0;
        xi1 = ni1; xf1 = nf1; xg1 = ng1; xo1 = no1;
    }

    float v0 = h0 * wfcv;
    float v1 = h1 * wfcv;
    #pragma unroll
    for (int o = 16; o > 0; o >>= 1) {
        v0 += __shfl_xor_sync(0xffffffffu, v0, o);
        v1 += __shfl_xor_sync(0xffffffffu, v1, o);
    }
    if (j == 0) {
        float bb = bfc[0];
        out[b0]     = v0 + bb;
        out[b0 + 1] = v1 + bb;
    }
}

// ---------------------------------------------------------------------------
extern "C" void kernel_launch(void* const* d_in, const int* in_sizes, int n_in,
                              void* d_out, int out_size)
{
    const float* x   = (const float*)d_in[0];
    const float* Wih = (const float*)d_in[1];
    const float* Whh = (const float*)d_in[2];
    const float* bih = (const float*)d_in[3];
    const float* bhh = (const float*)d_in[4];
    const float* Wfc = (const float*)d_in[5];
    const float* bfc = (const float*)d_in[6];
    float* out = (float*)d_out;

    cudaFuncSetAttribute(k1_wmma, cudaFuncAttributeMaxDynamicSharedMemorySize, SM_TOT);

    k1_wmma<<<(CB * CT) / (128 * K1T), 256, SM_TOT>>>(x, Wih);
    k2_rnn<<<CB / (2 * K2W), 32 * K2W>>>(Whh, bih, bhh, Wfc, bfc, out);
}